// round 7
// baseline (speedup 1.0000x reference)
#include <cuda_runtime.h>
#include <cstdint>

// SpottingLoss: greedy bipartite matching + YOLO-style loss.
// B=2048 batches, N=64 slots, F=19 features. One 64-thread CTA per batch.
// R6: single kernel (device-scratch grid reduction, no zero launch),
//     y_pred tile staged to smem (epilogue = LDS, not post-matching DRAM),
//     y_true features prefetched to regs before matching (latency overlap).
// Matching core (R5): phase-1 eliminated, pm-poison free-set, 8x8 tree argmax.

#define N_ 64
#define F_ 19
#define LAMBDA_COORD 5.0f
#define LAMBDA_NOOBJ 0.5f
#define FULLM 0xFFFFFFFFu

// Grid-reduction scratch. Zero-initialized at module load; the LAST block of
// every launch resets both to zero, so each graph replay starts clean.
__device__ float    g_acc   = 0.0f;
__device__ unsigned g_count = 0u;

// Column-acceptance key: (value bits << 32) | ~row. Proposal values are > 0,
// so float bits are monotone; larger key = larger value, then lower row index
// — exactly the reference's argmax-over-rows tie-breaking.
__device__ __forceinline__ unsigned long long mk_key(float v, int row) {
    return ((unsigned long long)__float_as_uint(v) << 32) |
           (unsigned long long)(FULLM - (unsigned)row);
}

__global__ __launch_bounds__(N_) void spotting_loss_kernel(
    const float* __restrict__ y_true,
    const float* __restrict__ y_pred,
    float* __restrict__ out)
{
    // yp_s: full y_pred tile (row stride 19, coprime with 32 banks -> LDS
    // reads of a row by different threads are conflict-free).
    __shared__ float yp_s[N_ * F_];
    // pm[j] = y_pred[j][1] while column j is free; poisoned to 3.0f once
    // matched (v = 1-|x-3| < 0 never beats a free column's v > 0).
    // After matching, pm[j]==3.0f doubles as "column taken" flag.
    __shared__ float pm[N_];
    __shared__ unsigned long long colkey[N_];
    __shared__ float red[2];

    const int b   = blockIdx.x;
    const int tid = threadIdx.x;

    const float* gt = y_true + (size_t)b * (N_ * F_);
    const float* gp = y_pred + (size_t)b * (N_ * F_);

    // Own y_true row scalars (scattered loads, issued first).
    const float alpha = __ldg(gt + tid * F_ + 0);   // exactly 0.0f or 1.0f
    const float x     = __ldg(gt + tid * F_ + 1);

    // Coalesced staging of the entire y_pred tile (19 iters, stride 64).
    for (int idx = tid; idx < N_ * F_; idx += N_)
        yp_s[idx] = __ldg(gp + idx);

    // Prefetch own y_true features for the alpha=1 epilogue; these DRAM loads
    // overlap with the whole matching loop instead of stalling the epilogue.
    float gtf[F_ - 2];
    if (alpha > 0.5f) {
#pragma unroll
        for (int f = 0; f < F_ - 2; ++f)
            gtf[f] = __ldg(gt + tid * F_ + 2 + f);
    }

    colkey[tid] = 0ull;           // init once; never reset (round invariant)
    __syncthreads();
    pm[tid] = yp_s[tid * F_ + 1];
    __syncthreads();

    int  perm   = 0;
    bool active = (alpha > 0.5f);

    // Invariant: every column proposed in a round is matched in that round,
    // so colkey entries are never reused and pm poison is the only free-set.
    for (;;) {
        if (__syncthreads_count(active) == 0) break;  // barrier A
        // (also orders last round's pm poison writes before this scan)

        int bj = 0;
        if (active) {
            // Two-level argmax over all 64 columns: 8 independent chunk
            // chains (ILP=8), then serial combine. Strict > keeps the
            // lowest index on ties in both levels = JAX argmax semantics.
            float cv[8]; int cj[8];
#pragma unroll
            for (int c = 0; c < 8; ++c) {
                float bv = -10.0f; int bi = c * 8;
#pragma unroll
                for (int k = 0; k < 8; ++k) {
                    int j = c * 8 + k;
                    float v = 1.0f - fabsf(x - pm[j]);
                    if (v > bv) { bv = v; bi = j; }
                }
                cv[c] = bv; cj[c] = bi;
            }
            float bv = cv[0]; bj = cj[0];
#pragma unroll
            for (int c = 1; c < 8; ++c)
                if (cv[c] > bv) { bv = cv[c]; bj = cj[c]; }

            atomicMax(&colkey[bj], mk_key(bv, tid));
        }
        __syncthreads();                              // barrier B

        if (active) {
            unsigned wr = FULLM - (unsigned)(colkey[bj] & 0xFFFFFFFFull);
            if (wr == (unsigned)tid) {                // column accepted us
                perm   = bj;
                active = false;
                pm[bj] = 3.0f;    // poison: single writer, ordered by barrier A
            }
        }
    }
    __syncthreads();   // pm poison flags final before epilogue reads

    float term = 0.0f;

    // alpha=1 row term: full YOLO loss vs permuted prediction row (all LDS).
    if (alpha > 0.5f) {
        const float* ypr = &yp_s[perm * F_];
        const float d0 = 1.0f - ypr[0];
        const float dx = x - ypr[1];
        float s = 0.0f;
#pragma unroll
        for (int f = 0; f < F_ - 2; ++f) {
            float d = gtf[f] - ypr[f + 2];
            s += d * d;
        }
        term += LAMBDA_COORD * dx * dx + d0 * d0 + s;
    }

    // alpha=0 contribution, per COLUMN: every column not taken in phase 0 is
    // assigned to exactly one alpha=0 row, contributing 0.5*yp[col,0]^2
    // regardless of which row got it.
    if (pm[tid] != 3.0f) {
        float p0 = yp_s[tid * F_ + 0];
        term += LAMBDA_NOOBJ * p0 * p0;
    }

    // Block reduction (2 warps), then grid reduction via device scratch.
#pragma unroll
    for (int o = 16; o; o >>= 1) term += __shfl_down_sync(FULLM, term, o);
    if ((tid & 31) == 0) red[tid >> 5] = term;
    __syncthreads();

    if (tid == 0) {
        atomicAdd(&g_acc, red[0] + red[1]);
        __threadfence();
        unsigned ticket = atomicAdd(&g_count, 1u);
        if (ticket == gridDim.x - 1) {                // last block finalizes
            float total = atomicAdd(&g_acc, 0.0f);    // coherent read
            out[0]  = total;
            g_acc   = 0.0f;                           // reset for next replay
            g_count = 0u;
        }
    }
}

extern "C" void kernel_launch(void* const* d_in, const int* in_sizes, int n_in,
                              void* d_out, int out_size)
{
    const float* y_true = (const float*)d_in[0];
    const float* y_pred = (const float*)d_in[1];
    float* out = (float*)d_out;

    int batches = in_sizes[0] / (N_ * F_);   // 2048
    spotting_loss_kernel<<<batches, N_>>>(y_true, y_pred, out);
}

// round 8
// speedup vs baseline: 1.1379x; 1.1379x over previous
#include <cuda_runtime.h>
#include <cstdint>

// SpottingLoss: greedy bipartite matching + YOLO-style loss.
// B=2048 batches, N=64 slots, F=19 features. One 64-thread CTA per batch.
// R7 = R5 dataflow (minimal 3-load startup; epilogue reads global directly —
//      front-batched staging REGRESSES via cross-CTA L1tex-queue contention)
//      + R6 single-kernel grid reduction (no separate zero launch).
// Matching core: phase-1 eliminated, pm-poison free-set, 8x8 tree argmax.

#define N_ 64
#define F_ 19
#define LAMBDA_COORD 5.0f
#define LAMBDA_NOOBJ 0.5f
#define FULLM 0xFFFFFFFFu

// Grid-reduction scratch. Zero-initialized at module load; the LAST block of
// every launch resets both, so each graph replay starts clean.
__device__ float    g_acc   = 0.0f;
__device__ unsigned g_count = 0u;

// Column-acceptance key: (value bits << 32) | ~row. Proposal values are > 0,
// so float bits are monotone; larger key = larger value, then lower row index
// — exactly the reference's argmax-over-rows tie-breaking.
__device__ __forceinline__ unsigned long long mk_key(float v, int row) {
    return ((unsigned long long)__float_as_uint(v) << 32) |
           (unsigned long long)(FULLM - (unsigned)row);
}

__global__ __launch_bounds__(N_) void spotting_loss_kernel(
    const float* __restrict__ y_true,
    const float* __restrict__ y_pred,
    float* __restrict__ out)
{
    // pm[j] = y_pred[j][1] while column j is free; poisoned to 3.0f once
    // matched (v = 1-|x-3| < 0 never beats a free column's v > 0).
    // After matching, pm[j]==3.0f doubles as the "column taken" flag.
    __shared__ float pm[N_];
    __shared__ unsigned long long colkey[N_];
    __shared__ float red[2];

    const int b   = blockIdx.x;
    const int tid = threadIdx.x;

    const float* gt = y_true + (size_t)b * (N_ * F_);
    const float* gp = y_pred + (size_t)b * (N_ * F_);

    // Minimal startup footprint: exactly 3 loads per thread.
    const float alpha = __ldg(gt + tid * F_ + 0);   // exactly 0.0f or 1.0f
    const float x     = __ldg(gt + tid * F_ + 1);
    pm[tid]     = __ldg(gp + tid * F_ + 1);
    colkey[tid] = 0ull;           // init once; never reset (round invariant)
    __syncthreads();

    int  perm   = 0;
    bool active = (alpha > 0.5f);                   // only alpha=1 rows match

    // Invariant: every column proposed in a round is matched in that round,
    // so colkey entries are never reused and pm poison is the only free-set.
    for (;;) {
        if (__syncthreads_count(active) == 0) break;  // barrier A
        // (also orders last round's pm poison writes before this scan)

        int bj = 0;
        if (active) {
            // Two-level argmax over all 64 columns: 8 independent chunk
            // chains (ILP=8), then serial combine. Strict > keeps the
            // lowest index on ties in both levels = JAX argmax semantics.
            float cv[8]; int cj[8];
#pragma unroll
            for (int c = 0; c < 8; ++c) {
                float bv = -10.0f; int bi = c * 8;
#pragma unroll
                for (int k = 0; k < 8; ++k) {
                    int j = c * 8 + k;
                    float v = 1.0f - fabsf(x - pm[j]);
                    if (v > bv) { bv = v; bi = j; }
                }
                cv[c] = bv; cj[c] = bi;
            }
            float bv = cv[0]; bj = cj[0];
#pragma unroll
            for (int c = 1; c < 8; ++c)
                if (cv[c] > bv) { bv = cv[c]; bj = cj[c]; }

            atomicMax(&colkey[bj], mk_key(bv, tid));
        }
        __syncthreads();                              // barrier B

        if (active) {
            unsigned wr = FULLM - (unsigned)(colkey[bj] & 0xFFFFFFFFull);
            if (wr == (unsigned)tid) {                // column accepted us
                perm   = bj;
                active = false;
                pm[bj] = 3.0f;    // poison: single writer, ordered by barrier A
            }
        }
    }
    __syncthreads();   // pm poison flags final before epilogue reads

    float term = 0.0f;

    // alpha=1 row term: full YOLO loss vs permuted prediction row `perm`
    // (direct global reads; hidden by other resident CTAs' matching work).
    if (alpha > 0.5f) {
        const float* gtr = gt + tid * F_;
        const float* ypr = gp + perm * F_;
        const float d0 = 1.0f - __ldg(ypr + 0);
        const float dx = x - __ldg(ypr + 1);
        float s = 0.0f;
#pragma unroll
        for (int f = 2; f < F_; ++f) {
            float d = __ldg(gtr + f) - __ldg(ypr + f);
            s += d * d;
        }
        term += LAMBDA_COORD * dx * dx + d0 * d0 + s;
    }

    // alpha=0 contribution, per COLUMN: every column not taken in phase 0 is
    // assigned to exactly one alpha=0 row, contributing 0.5*yp[col,0]^2
    // regardless of which row got it.
    if (pm[tid] != 3.0f) {
        float p0 = __ldg(gp + tid * F_ + 0);
        term += LAMBDA_NOOBJ * p0 * p0;
    }

    // Block reduction (2 warps), then grid reduction via device scratch.
#pragma unroll
    for (int o = 16; o; o >>= 1) term += __shfl_down_sync(FULLM, term, o);
    if ((tid & 31) == 0) red[tid >> 5] = term;
    __syncthreads();

    if (tid == 0) {
        atomicAdd(&g_acc, red[0] + red[1]);
        __threadfence();
        unsigned ticket = atomicAdd(&g_count, 1u);
        if (ticket == gridDim.x - 1) {                // last block finalizes
            float total = atomicAdd(&g_acc, 0.0f);    // coherent read
            out[0]  = total;
            g_acc   = 0.0f;                           // reset for next replay
            g_count = 0u;
        }
    }
}

extern "C" void kernel_launch(void* const* d_in, const int* in_sizes, int n_in,
                              void* d_out, int out_size)
{
    const float* y_true = (const float*)d_in[0];
    const float* y_pred = (const float*)d_in[1];
    float* out = (float*)d_out;

    int batches = in_sizes[0] / (N_ * F_);   // 2048
    spotting_loss_kernel<<<batches, N_>>>(y_true, y_pred, out);
}